// round 9
// baseline (speedup 1.0000x reference)
#include <cuda_runtime.h>
#include <cuda_bf16.h>
#include <cstdint>

#define NN   10000
#define EE   160000
#define ET   170000
#define FINC 128
#define HID  512
#define NCLS 10

// ---------------- scratch ----------------
// activations h stored as dual-plane bf16 (hi+lo ~= fp32): 256 u32 pairs per row
__device__ uint32_t g_hhi[NN * 256];
__device__ uint32_t g_hlo[NN * 256];
__device__ uint32_t g_xphi[NN * 64];       // packed input x planes (64 pairs/row)
__device__ uint32_t g_xplo[NN * 64];
__device__ float g_xlr[NN * 1024];         // per-node [xl(512) | xr(512)] fp32
__device__ int   g_rowstart[NN + 1];
__device__ int   g_deg[NN];
__device__ int   g_cnt[NN];
__device__ int2  g_eix[ET];                // (src, dist_bits) in CSR order
__device__ int   g_i64;
// packed bf16 hi/lo weights in fragment-native tile order
#define WPK_B 0
#define WPK_L(i) (65536 + (i) * 524288)
__device__ uint32_t g_wpk[65536 + 3 * 524288];

__device__ __forceinline__ int ld_edge(const void* ei, long idx, int i64) {
    if (i64) return (int)((const long long*)ei)[idx];
    return ((const int*)ei)[idx];
}

__device__ __forceinline__ uint32_t pack_bf16x2(float lo, float hi) {
    uint32_t r;
    asm("cvt.rn.bf16x2.f32 %0, %1, %2;" : "=r"(r) : "f"(hi), "f"(lo));
    return r;
}
// split fp32 pair -> (hi u32, lo u32)
__device__ __forceinline__ void split_pair(float v0, float v1, uint32_t& hi, uint32_t& lo) {
    hi = pack_bf16x2(v0, v1);
    float r0 = v0 - __uint_as_float(hi << 16);
    float r1 = v1 - __uint_as_float(hi & 0xFFFF0000u);
    lo = pack_bf16x2(r0, r1);
}

// ---------------- zero + dtype detect + x plane pack ----------------
__global__ void k_zero(const unsigned int* ei, const float* __restrict__ x) {
    if (blockIdx.x == 0) {
        __shared__ unsigned int s[256];
        unsigned int o = 0;
        for (int i = threadIdx.x; i < 8192; i += 256) o |= ei[2 * i + 1];
        s[threadIdx.x] = o;
        __syncthreads();
        for (int off = 128; off; off >>= 1) {
            if (threadIdx.x < off) s[threadIdx.x] |= s[threadIdx.x + off];
            __syncthreads();
        }
        if (threadIdx.x == 0) g_i64 = (s[0] == 0u) ? 1 : 0;
    } else if (blockIdx.x <= 40) {
        int i = (blockIdx.x - 1) * 256 + threadIdx.x;
        if (i < NN) { g_deg[i] = 0; g_cnt[i] = 0; }
    } else {
        int i = (blockIdx.x - 41) * 256 + threadIdx.x;
        if (i < NN * 64) {
            float2 v = *(const float2*)(x + (long)i * 2);
            uint32_t hi, lo;
            split_pair(v.x, v.y, hi, lo);
            g_xphi[i] = hi;
            g_xplo[i] = lo;
        }
    }
}

// ---------------- weight pack: fragment-native bf16 hi/lo tiles ----------------
__global__ void k_pack(const float* __restrict__ Wb, const float* __restrict__ Wl,
                       const float* __restrict__ Wr) {
    const int TOT = 65536 + 3 * 524288;
    for (int u = blockIdx.x * 1024 + threadIdx.x * 4, c = 0; c < 4; c++, u++) {
        if (u >= TOT) return;
        const float* W; int Nc, off, layer_n0 = 0;
        const float* W2 = 0;
        if (u < 65536) { W = Wb; Nc = HID; off = u; }
        else {
            int li = (u - 65536) / 524288;
            off = (u - 65536) % 524288;
            W = Wl + (long)li * HID * HID;
            W2 = Wr + (long)li * HID * HID;
            Nc = HID;
            layer_n0 = 1;
        }
        int tile = off >> 12, v = off & 4095;
        int KT = (u < 65536) ? 4 : 16;
        int bnt = tile / KT, kt = tile % KT;
        int rr = v & 1, lane = (v >> 1) & 31, p = (v >> 6) & 1;
        int s = (v >> 7) & 1, nt = (v >> 8) & 15;
        int n = bnt * 128 + nt * 8 + (lane >> 2);
        int k = kt * 32 + s * 16 + (lane & 3) * 2 + rr * 8;
        const float* Ws = W;
        if (layer_n0 && n >= HID) { Ws = W2; n -= HID; }
        float w0 = Ws[(long)k * Nc + n];
        float w1 = Ws[(long)(k + 1) * Nc + n];
        uint32_t hib = pack_bf16x2(w0, w1);
        uint32_t outv;
        if (p == 0) outv = hib;
        else {
            float l0 = w0 - __uint_as_float(hib << 16);
            float l1 = w1 - __uint_as_float(hib & 0xFFFF0000u);
            outv = pack_bf16x2(l0, l1);
        }
        g_wpk[u] = outv;
    }
}

// ---------------- bf16x3 mma.sync GEMM, plane A inputs, cp.async 3-stage ----------------
#define STAGES 3
#define STG_BYTES 32768          // A hi 8KB + A lo 8KB + B 16KB
#define GSMEM_BYTES (STAGES * STG_BYTES)

__device__ __forceinline__ void mma16(float* d, const uint32_t* a, uint32_t b0, uint32_t b1) {
    asm volatile("mma.sync.aligned.m16n8k16.row.col.f32.bf16.bf16.f32 "
        "{%0,%1,%2,%3}, {%4,%5,%6,%7}, {%8,%9}, {%0,%1,%2,%3};"
        : "+f"(d[0]), "+f"(d[1]), "+f"(d[2]), "+f"(d[3])
        : "r"(a[0]), "r"(a[1]), "r"(a[2]), "r"(a[3]), "r"(b0), "r"(b1));
}

__device__ __forceinline__ void gemm_issue(const uint32_t* __restrict__ Ahi,
                                           const uint32_t* __restrict__ Alo,
                                           const uint32_t* __restrict__ wpk,
                                           char* smbase, int t, int kt, int KT,
                                           int rowPairs, int Mrem) {
    if (kt < KT) {
        char* As = smbase + (kt % STAGES) * STG_BYTES;
        char* Bs = As + 16384;
        const uint32_t* wsrc = wpk + (long)kt * 4096;
#pragma unroll
        for (int l = 0; l < 4; l++) {
            int ca = t + l * 256;                 // 0..1023
            // ---- A: 1024 16B chunks (512 hi + 512 lo) in fragment-native layout
            int idx = ca & 511, plane = ca >> 9;
            int m = idx >> 2, s = (idx >> 1) & 1, c = idx & 1;
            int mt = m >> 4, half = (m >> 3) & 1, g8 = m & 7;
            uint32_t da = (uint32_t)__cvta_generic_to_shared(
                As + ((plane * 2048 + ((mt * 2 + s) * 4 + half + 2 * c) * 32 + g8 * 4) << 2));
            const uint32_t* base = plane ? Alo : Ahi;
            const uint32_t* sa = base + (long)(m < Mrem ? m : 0) * rowPairs
                                 + kt * 16 + s * 8 + 4 * c;
            int sz = (m < Mrem) ? 16 : 0;
            asm volatile("cp.async.cg.shared.global [%0], [%1], 16, %2;"
                :: "r"(da), "l"(sa), "r"(sz));
            // ---- B: 1024 16B chunks, linear
            uint32_t db = (uint32_t)__cvta_generic_to_shared(Bs + ca * 16);
            asm volatile("cp.async.cg.shared.global [%0], [%1], 16;"
                :: "r"(db), "l"(wsrc + ca * 4));
        }
    }
    asm volatile("cp.async.commit_group;" ::: "memory");
}

// act=1: write h planes (+elu). act=0: write fp32 C (xlr).
__global__ void __launch_bounds__(256, 2)
k_mma_gemm(const uint32_t* __restrict__ Ahi, const uint32_t* __restrict__ Alo,
           const uint32_t* __restrict__ wpk,
           const float* __restrict__ bias_l, const float* __restrict__ bias_r,
           float* __restrict__ C, int M, int K, int Nc, int act) {
    extern __shared__ char sm[];
    int t = threadIdx.x, wid = t >> 5, lane = t & 31;
    int bm = blockIdx.y * 128, bn = blockIdx.x * 128;
    int wmt = (wid & 3) * 2;
    int wnt = (wid >> 2) * 8;
    int g = lane >> 2, qc = lane & 3;
    int Mrem = M - bm;
    int KT = K >> 5, rowPairs = K >> 1;
    const uint32_t* wpkb = wpk + (long)blockIdx.x * KT * 4096;

    float d[2][8][4];
#pragma unroll
    for (int i = 0; i < 2; i++)
#pragma unroll
        for (int j = 0; j < 8; j++)
#pragma unroll
            for (int c = 0; c < 4; c++) d[i][j][c] = 0.f;

    const uint32_t* Ahb = Ahi + (long)bm * rowPairs;
    const uint32_t* Alb = Alo + (long)bm * rowPairs;

    gemm_issue(Ahb, Alb, wpkb, sm, t, 0, KT, rowPairs, Mrem);
    gemm_issue(Ahb, Alb, wpkb, sm, t, 1, KT, rowPairs, Mrem);

    for (int kt = 0; kt < KT; kt++) {
        asm volatile("cp.async.wait_group 1;" ::: "memory");
        __syncthreads();
        gemm_issue(Ahb, Alb, wpkb, sm, t, kt + 2, KT, rowPairs, Mrem);

        const uint32_t* Ap = (const uint32_t*)(sm + (kt % STAGES) * STG_BYTES);
        const uint32_t* Bs = Ap + 4096;
#pragma unroll
        for (int s = 0; s < 2; s++) {
            uint32_t ahi[2][4], alo[2][4];
#pragma unroll
            for (int mt = 0; mt < 2; mt++) {
                int base = ((wmt + mt) * 2 + s) * 128 + lane;
#pragma unroll
                for (int r = 0; r < 4; r++) {
                    ahi[mt][r] = Ap[base + r * 32];
                    alo[mt][r] = Ap[2048 + base + r * 32];
                }
            }
#pragma unroll
            for (int nt = 0; nt < 8; nt++) {
                int ng = wnt + nt;
                const uint32_t* bp = Bs + ((ng * 2 + s) * 2) * 64 + lane * 2;
                uint32_t bh0 = bp[0], bh1 = bp[1];
                uint32_t bl0 = bp[64], bl1 = bp[65];
#pragma unroll
                for (int mt = 0; mt < 2; mt++) {
                    mma16(d[mt][nt], ahi[mt], bh0, bh1);
                    mma16(d[mt][nt], ahi[mt], bl0, bl1);
                    mma16(d[mt][nt], alo[mt], bh0, bh1);
                }
            }
        }
    }

#pragma unroll
    for (int nt = 0; nt < 8; nt++) {
        int col = bn + (wnt + nt) * 8 + qc * 2;
        float b0 = (col < HID) ? bias_l[col] : bias_r[col - HID];
        float b1 = (col + 1 < HID) ? bias_l[col + 1] : bias_r[col + 1 - HID];
#pragma unroll
        for (int mt = 0; mt < 2; mt++) {
            int row = bm + (wmt + mt) * 16 + g;
            float v0 = d[mt][nt][0] + b0, v1 = d[mt][nt][1] + b1;
            float v2 = d[mt][nt][2] + b0, v3 = d[mt][nt][3] + b1;
            if (act) {
                v0 = (v0 > 0.f) ? v0 : expm1f(v0);
                v1 = (v1 > 0.f) ? v1 : expm1f(v1);
                v2 = (v2 > 0.f) ? v2 : expm1f(v2);
                v3 = (v3 > 0.f) ? v3 : expm1f(v3);
                uint32_t hi, lo;
                if (row < M) {
                    split_pair(v0, v1, hi, lo);
                    g_hhi[(long)row * 256 + (col >> 1)] = hi;
                    g_hlo[(long)row * 256 + (col >> 1)] = lo;
                }
                if (row + 8 < M) {
                    split_pair(v2, v3, hi, lo);
                    g_hhi[(long)(row + 8) * 256 + (col >> 1)] = hi;
                    g_hlo[(long)(row + 8) * 256 + (col >> 1)] = lo;
                }
            } else {
                if (row < M)     *(float2*)(C + (long)row * Nc + col)       = make_float2(v0, v1);
                if (row + 8 < M) *(float2*)(C + (long)(row + 8) * Nc + col) = make_float2(v2, v3);
            }
        }
    }
}

// ---------------- CSR ----------------
__global__ void k_count(const void* ei) {
    int i64 = g_i64;
    for (int e = blockIdx.x * blockDim.x + threadIdx.x; e < ET; e += gridDim.x * blockDim.x) {
        int d = (e < EE) ? ld_edge(ei, (long)EE + e, i64) : (e - EE);
        atomicAdd(&g_deg[d], 1);
    }
}
__global__ void k_scan() {
    __shared__ int part[1024];
    const int CH = (NN + 1023) / 1024;
    int t = threadIdx.x;
    int local[CH];
    int s = 0;
#pragma unroll
    for (int i = 0; i < CH; i++) {
        int idx = t * CH + i;
        int v = (idx < NN) ? g_deg[idx] : 0;
        local[i] = s; s += v;
    }
    part[t] = s;
    __syncthreads();
    int val = s;
    for (int off = 1; off < 1024; off <<= 1) {
        int add = (t >= off) ? part[t - off] : 0;
        __syncthreads();
        val += add; part[t] = val;
        __syncthreads();
    }
    int base = val - s;
#pragma unroll
    for (int i = 0; i < CH; i++) {
        int idx = t * CH + i;
        if (idx < NN) g_rowstart[idx] = base + local[i];
    }
    if (t == 1023) g_rowstart[NN] = val;
}
__global__ void k_fill(const void* ei, const float* __restrict__ dist) {
    int i64 = g_i64;
    for (int e = blockIdx.x * blockDim.x + threadIdx.x; e < ET; e += gridDim.x * blockDim.x) {
        int s, d; float dv;
        if (e < EE) {
            s = ld_edge(ei, e, i64);
            d = ld_edge(ei, (long)EE + e, i64);
            dv = dist[e];
        } else { s = d = e - EE; dv = 0.f; }
        int pos = g_rowstart[d] + atomicAdd(&g_cnt[d], 1);
        g_eix[pos] = make_int2(s, __float_as_int(dv));
    }
}

// ---------------- fused GAT: warp-per-head, no-max softmax, 2-edge ILP ----------------
__global__ void __launch_bounds__(256)
k_gat(const float* __restrict__ We, const float* __restrict__ att,
      const float* __restrict__ bias, int apply_elu) {
    int n = blockIdx.x;
    int wid = threadIdx.x >> 5, lane = threadIdx.x & 31;
    int ch = wid * 64 + lane * 2;

    float2 we = *(const float2*)(We + ch);
    float2 at = *(const float2*)(att + ch);
    float2 xr = *(const float2*)(g_xlr + (long)n * 1024 + HID + ch);

    int r0 = g_rowstart[n];
    int deg = g_rowstart[n + 1] - r0;

    float ssum = 0.f;
    float2 acc = make_float2(0.f, 0.f);

    int j = 0;
    for (; j + 1 < deg; j += 2) {
        int2 e0 = __ldg(&g_eix[r0 + j]);
        int2 e1 = __ldg(&g_eix[r0 + j + 1]);
        float2 f0 = *(const float2*)(g_xlr + (long)e0.x * 1024 + ch);
        float2 f1 = *(const float2*)(g_xlr + (long)e1.x * 1024 + ch);
        float d0 = __int_as_float(e0.y), d1 = __int_as_float(e1.y);
        float a0 = f0.x + xr.x + d0 * we.x; a0 = (a0 > 0.f) ? a0 : 0.2f * a0;
        float b0 = f0.y + xr.y + d0 * we.y; b0 = (b0 > 0.f) ? b0 : 0.2f * b0;
        float a1 = f1.x + xr.x + d1 * we.x; a1 = (a1 > 0.f) ? a1 : 0.2f * a1;
        float b1 = f1.y + xr.y + d1 * we.y; b1 = (b1 > 0.f) ? b1 : 0.2f * b1;
        float p0 = a0 * at.x + b0 * at.y;
        float p1 = a1 * at.x + b1 * at.y;
#pragma unroll
        for (int o = 16; o; o >>= 1) {
            p0 += __shfl_xor_sync(0xffffffffu, p0, o);
            p1 += __shfl_xor_sync(0xffffffffu, p1, o);
        }
        float w0 = __expf(p0), w1 = __expf(p1);
        ssum += w0 + w1;
        acc.x += w0 * f0.x + w1 * f1.x;
        acc.y += w0 * f0.y + w1 * f1.y;
    }
    if (j < deg) {
        int2 e0 = __ldg(&g_eix[r0 + j]);
        float2 f0 = *(const float2*)(g_xlr + (long)e0.x * 1024 + ch);
        float d0 = __int_as_float(e0.y);
        float a0 = f0.x + xr.x + d0 * we.x; a0 = (a0 > 0.f) ? a0 : 0.2f * a0;
        float b0 = f0.y + xr.y + d0 * we.y; b0 = (b0 > 0.f) ? b0 : 0.2f * b0;
        float p0 = a0 * at.x + b0 * at.y;
#pragma unroll
        for (int o = 16; o; o >>= 1) p0 += __shfl_xor_sync(0xffffffffu, p0, o);
        float w0 = __expf(p0);
        ssum += w0;
        acc.x += w0 * f0.x;
        acc.y += w0 * f0.y;
    }
    float inv = 1.f / ssum;
    float o0 = acc.x * inv + bias[ch];
    float o1 = acc.y * inv + bias[ch + 1];
    if (apply_elu) {
        o0 = (o0 > 0.f) ? o0 : expm1f(o0);
        o1 = (o1 > 0.f) ? o1 : expm1f(o1);
    }
    uint32_t hi, lo;
    split_pair(o0, o1, hi, lo);
    g_hhi[(long)n * 256 + (ch >> 1)] = hi;
    g_hlo[(long)n * 256 + (ch >> 1)] = lo;
}

// ---------------- classifier (reads h planes) ----------------
__global__ __launch_bounds__(256)
void k_classifier(const float* __restrict__ Wa, const float* __restrict__ ba,
                  float* __restrict__ out) {
    __shared__ float sW[HID * NCLS];
    __shared__ float sb[NCLS];
    int t = threadIdx.x;
    for (int i = t; i < HID * NCLS; i += 256) sW[i] = Wa[i];
    if (t < NCLS) sb[t] = ba[t];
    __syncthreads();
    int row = blockIdx.x * 8 + (t >> 5);
    int lane = t & 31;
    if (row >= NN) return;
    float acc[NCLS];
#pragma unroll
    for (int c = 0; c < NCLS; c++) acc[c] = 0.f;
    for (int p = lane; p < 256; p += 32) {
        uint32_t hi = g_hhi[(long)row * 256 + p];
        uint32_t lo = g_hlo[(long)row * 256 + p];
        float v0 = __uint_as_float(hi << 16) + __uint_as_float(lo << 16);
        float v1 = __uint_as_float(hi & 0xFFFF0000u) + __uint_as_float(lo & 0xFFFF0000u);
        v0 = (v0 > 0.f) ? v0 : expm1f(v0);
        v1 = (v1 > 0.f) ? v1 : expm1f(v1);
#pragma unroll
        for (int c = 0; c < NCLS; c++)
            acc[c] += v0 * sW[(2 * p) * NCLS + c] + v1 * sW[(2 * p + 1) * NCLS + c];
    }
#pragma unroll
    for (int c = 0; c < NCLS; c++)
#pragma unroll
        for (int off = 16; off; off >>= 1)
            acc[c] += __shfl_xor_sync(0xffffffffu, acc[c], off);
    if (lane == 0) {
        float mx = -3.4e38f;
#pragma unroll
        for (int c = 0; c < NCLS; c++) { acc[c] += sb[c]; mx = fmaxf(mx, acc[c]); }
        float s = 0.f;
#pragma unroll
        for (int c = 0; c < NCLS; c++) s += __expf(acc[c] - mx);
        float lse = mx + __logf(s);
#pragma unroll
        for (int c = 0; c < NCLS; c++)
            out[(long)row * NCLS + c] = acc[c] - lse;
    }
}

// ---------------- launcher ----------------
extern "C" void kernel_launch(void* const* d_in, const int* in_sizes, int n_in,
                              void* d_out, int out_size) {
    const float* x    = (const float*)d_in[0];
    const void*  ei   = d_in[1];
    const float* dist = (const float*)d_in[2];
    const float* Wb   = (const float*)d_in[3];
    const float* bb   = (const float*)d_in[4];
    const float* Wl   = (const float*)d_in[5];
    const float* bl   = (const float*)d_in[6];
    const float* Wr   = (const float*)d_in[7];
    const float* br   = (const float*)d_in[8];
    const float* We   = (const float*)d_in[9];
    const float* att  = (const float*)d_in[10];
    const float* bc   = (const float*)d_in[11];
    const float* Wa   = (const float*)d_in[12];
    const float* ba   = (const float*)d_in[13];
    float* out = (float*)d_out;

    float* p_xlr;
    uint32_t *p_wpk, *p_hhi, *p_hlo, *p_xphi, *p_xplo;
    cudaGetSymbolAddress((void**)&p_xlr, g_xlr);
    cudaGetSymbolAddress((void**)&p_wpk, g_wpk);
    cudaGetSymbolAddress((void**)&p_hhi, g_hhi);
    cudaGetSymbolAddress((void**)&p_hlo, g_hlo);
    cudaGetSymbolAddress((void**)&p_xphi, g_xphi);
    cudaGetSymbolAddress((void**)&p_xplo, g_xplo);

    cudaFuncSetAttribute(k_mma_gemm, cudaFuncAttributeMaxDynamicSharedMemorySize, GSMEM_BYTES);

    k_zero<<<41 + (NN * 64 + 255) / 256, 256>>>((const unsigned int*)ei, x); // 0
    k_pack<<<1600, 256>>>(Wb, Wl, Wr);                                       // 1
    k_mma_gemm<<<dim3(4, 79), 256, GSMEM_BYTES>>>(p_xphi, p_xplo, p_wpk + WPK_B,
                                                  bb, bb, nullptr,
                                                  NN, FINC, HID, 1);         // 2
    k_mma_gemm<<<dim3(8, 79), 256, GSMEM_BYTES>>>(p_hhi, p_hlo, p_wpk + WPK_L(0),
                                                  bl, br, p_xlr,
                                                  NN, HID, 1024, 0);         // 3 <- profiled
    k_count<<<664, 256>>>(ei);                                               // 4
    k_scan<<<1, 1024>>>();                                                   // 5
    k_fill<<<664, 256>>>(ei, dist);                                          // 6
    k_gat<<<NN, 256>>>(We, att, bc, 1);                                      // 7
    for (int i = 1; i < 3; i++) {
        k_mma_gemm<<<dim3(8, 79), 256, GSMEM_BYTES>>>(p_hhi, p_hlo, p_wpk + WPK_L(i),
                                                      bl + i * HID, br + i * HID,
                                                      p_xlr, NN, HID, 1024, 0);
        k_gat<<<NN, 256>>>(We + i * HID, att + i * HID, bc + i * HID, (i < 2) ? 1 : 0);
    }
    k_classifier<<<(NN + 7) / 8, 256>>>(Wa, ba, out);
}

// round 10
// speedup vs baseline: 1.0030x; 1.0030x over previous
#include <cuda_runtime.h>
#include <cuda_bf16.h>
#include <cstdint>

#define NN   10000
#define EE   160000
#define ET   170000
#define FINC 128
#define HID  512
#define NCLS 10

// ---------------- scratch ----------------
// activations h stored as dual-plane bf16 (hi+lo ~= fp32): 256 u32 pairs per row
__device__ uint32_t g_hhi[NN * 256];
__device__ uint32_t g_hlo[NN * 256];
__device__ uint32_t g_xphi[NN * 64];       // packed input x planes (64 pairs/row)
__device__ uint32_t g_xplo[NN * 64];
__device__ float g_xlr[NN * 1024];         // per-node [xl(512) | xr(512)] fp32
__device__ int   g_rowstart[NN + 1];
__device__ int   g_deg[NN];
__device__ int   g_cnt[NN];
__device__ int2  g_eix[ET];                // (src, dist_bits) in CSR order
__device__ int   g_i64;
// packed bf16 hi/lo weights in fragment-native tile order
#define WPK_B 0
#define WPK_L(i) (65536 + (i) * 524288)
__device__ uint32_t g_wpk[65536 + 3 * 524288];

__device__ __forceinline__ int ld_edge(const void* ei, long idx, int i64) {
    if (i64) return (int)((const long long*)ei)[idx];
    return ((const int*)ei)[idx];
}

__device__ __forceinline__ uint32_t pack_bf16x2(float lo, float hi) {
    uint32_t r;
    asm("cvt.rn.bf16x2.f32 %0, %1, %2;" : "=r"(r) : "f"(hi), "f"(lo));
    return r;
}
// split fp32 pair -> (hi u32, lo u32)
__device__ __forceinline__ void split_pair(float v0, float v1, uint32_t& hi, uint32_t& lo) {
    hi = pack_bf16x2(v0, v1);
    float r0 = v0 - __uint_as_float(hi << 16);
    float r1 = v1 - __uint_as_float(hi & 0xFFFF0000u);
    lo = pack_bf16x2(r0, r1);
}

// ---------------- zero + dtype detect + x plane pack ----------------
__global__ void k_zero(const unsigned int* ei, const float* __restrict__ x) {
    if (blockIdx.x == 0) {
        __shared__ unsigned int s[256];
        unsigned int o = 0;
        for (int i = threadIdx.x; i < 8192; i += 256) o |= ei[2 * i + 1];
        s[threadIdx.x] = o;
        __syncthreads();
        for (int off = 128; off; off >>= 1) {
            if (threadIdx.x < off) s[threadIdx.x] |= s[threadIdx.x + off];
            __syncthreads();
        }
        if (threadIdx.x == 0) g_i64 = (s[0] == 0u) ? 1 : 0;
    } else if (blockIdx.x <= 40) {
        int i = (blockIdx.x - 1) * 256 + threadIdx.x;
        if (i < NN) { g_deg[i] = 0; g_cnt[i] = 0; }
    } else {
        int i = (blockIdx.x - 41) * 256 + threadIdx.x;
        if (i < NN * 64) {
            float2 v = *(const float2*)(x + (long)i * 2);
            uint32_t hi, lo;
            split_pair(v.x, v.y, hi, lo);
            g_xphi[i] = hi;
            g_xplo[i] = lo;
        }
    }
}

// ---------------- weight pack: fragment-native bf16 hi/lo tiles ----------------
__global__ void k_pack(const float* __restrict__ Wb, const float* __restrict__ Wl,
                       const float* __restrict__ Wr) {
    const int TOT = 65536 + 3 * 524288;
    for (int u = blockIdx.x * 1024 + threadIdx.x * 4, c = 0; c < 4; c++, u++) {
        if (u >= TOT) return;
        const float* W; int Nc, off, layer_n0 = 0;
        const float* W2 = 0;
        if (u < 65536) { W = Wb; Nc = HID; off = u; }
        else {
            int li = (u - 65536) / 524288;
            off = (u - 65536) % 524288;
            W = Wl + (long)li * HID * HID;
            W2 = Wr + (long)li * HID * HID;
            Nc = HID;
            layer_n0 = 1;
        }
        int tile = off >> 12, v = off & 4095;
        int KT = (u < 65536) ? 4 : 16;
        int bnt = tile / KT, kt = tile % KT;
        int rr = v & 1, lane = (v >> 1) & 31, p = (v >> 6) & 1;
        int s = (v >> 7) & 1, nt = (v >> 8) & 15;
        int n = bnt * 128 + nt * 8 + (lane >> 2);
        int k = kt * 32 + s * 16 + (lane & 3) * 2 + rr * 8;
        const float* Ws = W;
        if (layer_n0 && n >= HID) { Ws = W2; n -= HID; }
        float w0 = Ws[(long)k * Nc + n];
        float w1 = Ws[(long)(k + 1) * Nc + n];
        uint32_t hib = pack_bf16x2(w0, w1);
        uint32_t outv;
        if (p == 0) outv = hib;
        else {
            float l0 = w0 - __uint_as_float(hib << 16);
            float l1 = w1 - __uint_as_float(hib & 0xFFFF0000u);
            outv = pack_bf16x2(l0, l1);
        }
        g_wpk[u] = outv;
    }
}

// ---------------- bf16x3 mma.sync GEMM, plane A inputs, cp.async 3-stage ----------------
#define STAGES 3
#define STG_BYTES 32768          // A hi 8KB + A lo 8KB + B 16KB
#define GSMEM_BYTES (STAGES * STG_BYTES)

__device__ __forceinline__ void mma16(float* d, const uint32_t* a, uint32_t b0, uint32_t b1) {
    asm volatile("mma.sync.aligned.m16n8k16.row.col.f32.bf16.bf16.f32 "
        "{%0,%1,%2,%3}, {%4,%5,%6,%7}, {%8,%9}, {%0,%1,%2,%3};"
        : "+f"(d[0]), "+f"(d[1]), "+f"(d[2]), "+f"(d[3])
        : "r"(a[0]), "r"(a[1]), "r"(a[2]), "r"(a[3]), "r"(b0), "r"(b1));
}

__device__ __forceinline__ void gemm_issue(const uint32_t* __restrict__ Ahi,
                                           const uint32_t* __restrict__ Alo,
                                           const uint32_t* __restrict__ wpk,
                                           char* smbase, int t, int kt, int KT,
                                           int rowPairs, int Mrem) {
    if (kt < KT) {
        char* As = smbase + (kt % STAGES) * STG_BYTES;
        char* Bs = As + 16384;
        const uint32_t* wsrc = wpk + (long)kt * 4096;
#pragma unroll
        for (int l = 0; l < 4; l++) {
            int ca = t + l * 256;                 // 0..1023
            // ---- A: 1024 16B chunks (512 hi + 512 lo) in fragment-native layout
            int idx = ca & 511, plane = ca >> 9;
            int m = idx >> 2, s = (idx >> 1) & 1, c = idx & 1;
            int mt = m >> 4, half = (m >> 3) & 1, g8 = m & 7;
            uint32_t da = (uint32_t)__cvta_generic_to_shared(
                As + ((plane * 2048 + ((mt * 2 + s) * 4 + half + 2 * c) * 32 + g8 * 4) << 2));
            const uint32_t* base = plane ? Alo : Ahi;
            const uint32_t* sa = base + (long)(m < Mrem ? m : 0) * rowPairs
                                 + kt * 16 + s * 8 + 4 * c;
            int sz = (m < Mrem) ? 16 : 0;
            asm volatile("cp.async.cg.shared.global [%0], [%1], 16, %2;"
                :: "r"(da), "l"(sa), "r"(sz));
            // ---- B: 1024 16B chunks, linear
            uint32_t db = (uint32_t)__cvta_generic_to_shared(Bs + ca * 16);
            asm volatile("cp.async.cg.shared.global [%0], [%1], 16;"
                :: "r"(db), "l"(wsrc + ca * 4));
        }
    }
    asm volatile("cp.async.commit_group;" ::: "memory");
}

// act=1: write h planes (+elu). act=0: write fp32 C (xlr).
__global__ void __launch_bounds__(256, 2)
k_mma_gemm(const uint32_t* __restrict__ Ahi, const uint32_t* __restrict__ Alo,
           const uint32_t* __restrict__ wpk,
           const float* __restrict__ bias_l, const float* __restrict__ bias_r,
           float* __restrict__ C, int M, int K, int Nc, int act) {
    extern __shared__ char sm[];
    int t = threadIdx.x, wid = t >> 5, lane = t & 31;
    int bm = blockIdx.y * 128, bn = blockIdx.x * 128;
    int wmt = (wid & 3) * 2;
    int wnt = (wid >> 2) * 8;
    int g = lane >> 2, qc = lane & 3;
    int Mrem = M - bm;
    int KT = K >> 5, rowPairs = K >> 1;
    const uint32_t* wpkb = wpk + (long)blockIdx.x * KT * 4096;

    float d[2][8][4];
#pragma unroll
    for (int i = 0; i < 2; i++)
#pragma unroll
        for (int j = 0; j < 8; j++)
#pragma unroll
            for (int c = 0; c < 4; c++) d[i][j][c] = 0.f;

    const uint32_t* Ahb = Ahi + (long)bm * rowPairs;
    const uint32_t* Alb = Alo + (long)bm * rowPairs;

    gemm_issue(Ahb, Alb, wpkb, sm, t, 0, KT, rowPairs, Mrem);
    gemm_issue(Ahb, Alb, wpkb, sm, t, 1, KT, rowPairs, Mrem);

    for (int kt = 0; kt < KT; kt++) {
        asm volatile("cp.async.wait_group 1;" ::: "memory");
        __syncthreads();
        gemm_issue(Ahb, Alb, wpkb, sm, t, kt + 2, KT, rowPairs, Mrem);

        const uint32_t* Ap = (const uint32_t*)(sm + (kt % STAGES) * STG_BYTES);
        const uint32_t* Bs = Ap + 4096;
#pragma unroll
        for (int s = 0; s < 2; s++) {
            uint32_t ahi[2][4], alo[2][4];
#pragma unroll
            for (int mt = 0; mt < 2; mt++) {
                int base = ((wmt + mt) * 2 + s) * 128 + lane;
#pragma unroll
                for (int r = 0; r < 4; r++) {
                    ahi[mt][r] = Ap[base + r * 32];
                    alo[mt][r] = Ap[2048 + base + r * 32];
                }
            }
#pragma unroll
            for (int nt = 0; nt < 8; nt++) {
                int ng = wnt + nt;
                const uint32_t* bp = Bs + ((ng * 2 + s) * 2) * 64 + lane * 2;
                uint32_t bh0 = bp[0], bh1 = bp[1];
                uint32_t bl0 = bp[64], bl1 = bp[65];
#pragma unroll
                for (int mt = 0; mt < 2; mt++) {
                    mma16(d[mt][nt], ahi[mt], bh0, bh1);
                    mma16(d[mt][nt], ahi[mt], bl0, bl1);
                    mma16(d[mt][nt], alo[mt], bh0, bh1);
                }
            }
        }
    }

#pragma unroll
    for (int nt = 0; nt < 8; nt++) {
        int col = bn + (wnt + nt) * 8 + qc * 2;
        float b0 = (col < HID) ? bias_l[col] : bias_r[col - HID];
        float b1 = (col + 1 < HID) ? bias_l[col + 1] : bias_r[col + 1 - HID];
#pragma unroll
        for (int mt = 0; mt < 2; mt++) {
            int row = bm + (wmt + mt) * 16 + g;
            float v0 = d[mt][nt][0] + b0, v1 = d[mt][nt][1] + b1;
            float v2 = d[mt][nt][2] + b0, v3 = d[mt][nt][3] + b1;
            if (act) {
                v0 = (v0 > 0.f) ? v0 : expm1f(v0);
                v1 = (v1 > 0.f) ? v1 : expm1f(v1);
                v2 = (v2 > 0.f) ? v2 : expm1f(v2);
                v3 = (v3 > 0.f) ? v3 : expm1f(v3);
                uint32_t hi, lo;
                if (row < M) {
                    split_pair(v0, v1, hi, lo);
                    g_hhi[(long)row * 256 + (col >> 1)] = hi;
                    g_hlo[(long)row * 256 + (col >> 1)] = lo;
                }
                if (row + 8 < M) {
                    split_pair(v2, v3, hi, lo);
                    g_hhi[(long)(row + 8) * 256 + (col >> 1)] = hi;
                    g_hlo[(long)(row + 8) * 256 + (col >> 1)] = lo;
                }
            } else {
                if (row < M)     *(float2*)(C + (long)row * Nc + col)       = make_float2(v0, v1);
                if (row + 8 < M) *(float2*)(C + (long)(row + 8) * Nc + col) = make_float2(v2, v3);
            }
        }
    }
}

// ---------------- CSR ----------------
__global__ void k_count(const void* ei) {
    int i64 = g_i64;
    for (int e = blockIdx.x * blockDim.x + threadIdx.x; e < ET; e += gridDim.x * blockDim.x) {
        int d = (e < EE) ? ld_edge(ei, (long)EE + e, i64) : (e - EE);
        atomicAdd(&g_deg[d], 1);
    }
}
__global__ void k_scan() {
    __shared__ int part[1024];
    const int CH = (NN + 1023) / 1024;
    int t = threadIdx.x;
    int local[CH];
    int s = 0;
#pragma unroll
    for (int i = 0; i < CH; i++) {
        int idx = t * CH + i;
        int v = (idx < NN) ? g_deg[idx] : 0;
        local[i] = s; s += v;
    }
    part[t] = s;
    __syncthreads();
    int val = s;
    for (int off = 1; off < 1024; off <<= 1) {
        int add = (t >= off) ? part[t - off] : 0;
        __syncthreads();
        val += add; part[t] = val;
        __syncthreads();
    }
    int base = val - s;
#pragma unroll
    for (int i = 0; i < CH; i++) {
        int idx = t * CH + i;
        if (idx < NN) g_rowstart[idx] = base + local[i];
    }
    if (t == 1023) g_rowstart[NN] = val;
}
__global__ void k_fill(const void* ei, const float* __restrict__ dist) {
    int i64 = g_i64;
    for (int e = blockIdx.x * blockDim.x + threadIdx.x; e < ET; e += gridDim.x * blockDim.x) {
        int s, d; float dv;
        if (e < EE) {
            s = ld_edge(ei, e, i64);
            d = ld_edge(ei, (long)EE + e, i64);
            dv = dist[e];
        } else { s = d = e - EE; dv = 0.f; }
        int pos = g_rowstart[d] + atomicAdd(&g_cnt[d], 1);
        g_eix[pos] = make_int2(s, __float_as_int(dv));
    }
}

// ---------------- fused GAT: warp-per-head, no-max softmax, 2-edge ILP ----------------
__global__ void __launch_bounds__(256)
k_gat(const float* __restrict__ We, const float* __restrict__ att,
      const float* __restrict__ bias, int apply_elu) {
    int n = blockIdx.x;
    int wid = threadIdx.x >> 5, lane = threadIdx.x & 31;
    int ch = wid * 64 + lane * 2;

    float2 we = *(const float2*)(We + ch);
    float2 at = *(const float2*)(att + ch);
    float2 xr = *(const float2*)(g_xlr + (long)n * 1024 + HID + ch);

    int r0 = g_rowstart[n];
    int deg = g_rowstart[n + 1] - r0;

    float ssum = 0.f;
    float2 acc = make_float2(0.f, 0.f);

    int j = 0;
    for (; j + 1 < deg; j += 2) {
        int2 e0 = __ldg(&g_eix[r0 + j]);
        int2 e1 = __ldg(&g_eix[r0 + j + 1]);
        float2 f0 = *(const float2*)(g_xlr + (long)e0.x * 1024 + ch);
        float2 f1 = *(const float2*)(g_xlr + (long)e1.x * 1024 + ch);
        float d0 = __int_as_float(e0.y), d1 = __int_as_float(e1.y);
        float a0 = f0.x + xr.x + d0 * we.x; a0 = (a0 > 0.f) ? a0 : 0.2f * a0;
        float b0 = f0.y + xr.y + d0 * we.y; b0 = (b0 > 0.f) ? b0 : 0.2f * b0;
        float a1 = f1.x + xr.x + d1 * we.x; a1 = (a1 > 0.f) ? a1 : 0.2f * a1;
        float b1 = f1.y + xr.y + d1 * we.y; b1 = (b1 > 0.f) ? b1 : 0.2f * b1;
        float p0 = a0 * at.x + b0 * at.y;
        float p1 = a1 * at.x + b1 * at.y;
#pragma unroll
        for (int o = 16; o; o >>= 1) {
            p0 += __shfl_xor_sync(0xffffffffu, p0, o);
            p1 += __shfl_xor_sync(0xffffffffu, p1, o);
        }
        float w0 = __expf(p0), w1 = __expf(p1);
        ssum += w0 + w1;
        acc.x += w0 * f0.x + w1 * f1.x;
        acc.y += w0 * f0.y + w1 * f1.y;
    }
    if (j < deg) {
        int2 e0 = __ldg(&g_eix[r0 + j]);
        float2 f0 = *(const float2*)(g_xlr + (long)e0.x * 1024 + ch);
        float d0 = __int_as_float(e0.y);
        float a0 = f0.x + xr.x + d0 * we.x; a0 = (a0 > 0.f) ? a0 : 0.2f * a0;
        float b0 = f0.y + xr.y + d0 * we.y; b0 = (b0 > 0.f) ? b0 : 0.2f * b0;
        float p0 = a0 * at.x + b0 * at.y;
#pragma unroll
        for (int o = 16; o; o >>= 1) p0 += __shfl_xor_sync(0xffffffffu, p0, o);
        float w0 = __expf(p0);
        ssum += w0;
        acc.x += w0 * f0.x;
        acc.y += w0 * f0.y;
    }
    float inv = 1.f / ssum;
    float o0 = acc.x * inv + bias[ch];
    float o1 = acc.y * inv + bias[ch + 1];
    if (apply_elu) {
        o0 = (o0 > 0.f) ? o0 : expm1f(o0);
        o1 = (o1 > 0.f) ? o1 : expm1f(o1);
    }
    uint32_t hi, lo;
    split_pair(o0, o1, hi, lo);
    g_hhi[(long)n * 256 + (ch >> 1)] = hi;
    g_hlo[(long)n * 256 + (ch >> 1)] = lo;
}

// ---------------- classifier (reads h planes) ----------------
__global__ __launch_bounds__(256)
void k_classifier(const float* __restrict__ Wa, const float* __restrict__ ba,
                  float* __restrict__ out) {
    __shared__ float sW[HID * NCLS];
    __shared__ float sb[NCLS];
    int t = threadIdx.x;
    for (int i = t; i < HID * NCLS; i += 256) sW[i] = Wa[i];
    if (t < NCLS) sb[t] = ba[t];
    __syncthreads();
    int row = blockIdx.x * 8 + (t >> 5);
    int lane = t & 31;
    if (row >= NN) return;
    float acc[NCLS];
#pragma unroll
    for (int c = 0; c < NCLS; c++) acc[c] = 0.f;
    for (int p = lane; p < 256; p += 32) {
        uint32_t hi = g_hhi[(long)row * 256 + p];
        uint32_t lo = g_hlo[(long)row * 256 + p];
        float v0 = __uint_as_float(hi << 16) + __uint_as_float(lo << 16);
        float v1 = __uint_as_float(hi & 0xFFFF0000u) + __uint_as_float(lo & 0xFFFF0000u);
        v0 = (v0 > 0.f) ? v0 : expm1f(v0);
        v1 = (v1 > 0.f) ? v1 : expm1f(v1);
#pragma unroll
        for (int c = 0; c < NCLS; c++)
            acc[c] += v0 * sW[(2 * p) * NCLS + c] + v1 * sW[(2 * p + 1) * NCLS + c];
    }
#pragma unroll
    for (int c = 0; c < NCLS; c++)
#pragma unroll
        for (int off = 16; off; off >>= 1)
            acc[c] += __shfl_xor_sync(0xffffffffu, acc[c], off);
    if (lane == 0) {
        float mx = -3.4e38f;
#pragma unroll
        for (int c = 0; c < NCLS; c++) { acc[c] += sb[c]; mx = fmaxf(mx, acc[c]); }
        float s = 0.f;
#pragma unroll
        for (int c = 0; c < NCLS; c++) s += __expf(acc[c] - mx);
        float lse = mx + __logf(s);
#pragma unroll
        for (int c = 0; c < NCLS; c++)
            out[(long)row * NCLS + c] = acc[c] - lse;
    }
}

// ---------------- launcher ----------------
extern "C" void kernel_launch(void* const* d_in, const int* in_sizes, int n_in,
                              void* d_out, int out_size) {
    const float* x    = (const float*)d_in[0];
    const void*  ei   = d_in[1];
    const float* dist = (const float*)d_in[2];
    const float* Wb   = (const float*)d_in[3];
    const float* bb   = (const float*)d_in[4];
    const float* Wl   = (const float*)d_in[5];
    const float* bl   = (const float*)d_in[6];
    const float* Wr   = (const float*)d_in[7];
    const float* br   = (const float*)d_in[8];
    const float* We   = (const float*)d_in[9];
    const float* att  = (const float*)d_in[10];
    const float* bc   = (const float*)d_in[11];
    const float* Wa   = (const float*)d_in[12];
    const float* ba   = (const float*)d_in[13];
    float* out = (float*)d_out;

    float* p_xlr;
    uint32_t *p_wpk, *p_hhi, *p_hlo, *p_xphi, *p_xplo;
    cudaGetSymbolAddress((void**)&p_xlr, g_xlr);
    cudaGetSymbolAddress((void**)&p_wpk, g_wpk);
    cudaGetSymbolAddress((void**)&p_hhi, g_hhi);
    cudaGetSymbolAddress((void**)&p_hlo, g_hlo);
    cudaGetSymbolAddress((void**)&p_xphi, g_xphi);
    cudaGetSymbolAddress((void**)&p_xplo, g_xplo);

    cudaFuncSetAttribute(k_mma_gemm, cudaFuncAttributeMaxDynamicSharedMemorySize, GSMEM_BYTES);

    k_zero<<<41 + (NN * 64 + 255) / 256, 256>>>((const unsigned int*)ei, x); // 0
    k_pack<<<1600, 256>>>(Wb, Wl, Wr);                                       // 1
    k_mma_gemm<<<dim3(4, 79), 256, GSMEM_BYTES>>>(p_xphi, p_xplo, p_wpk + WPK_B,
                                                  bb, bb, nullptr,
                                                  NN, FINC, HID, 1);         // 2
    k_mma_gemm<<<dim3(8, 79), 256, GSMEM_BYTES>>>(p_hhi, p_hlo, p_wpk + WPK_L(0),
                                                  bl, br, p_xlr,
                                                  NN, HID, 1024, 0);         // 3 <- profiled
    k_count<<<664, 256>>>(ei);                                               // 4
    k_scan<<<1, 1024>>>();                                                   // 5
    k_fill<<<664, 256>>>(ei, dist);                                          // 6
    k_gat<<<NN, 256>>>(We, att, bc, 1);                                      // 7
    for (int i = 1; i < 3; i++) {
        k_mma_gemm<<<dim3(8, 79), 256, GSMEM_BYTES>>>(p_hhi, p_hlo, p_wpk + WPK_L(i),
                                                      bl + i * HID, br + i * HID,
                                                      p_xlr, NN, HID, 1024, 0);
        k_gat<<<NN, 256>>>(We + i * HID, att + i * HID, bc + i * HID, (i < 2) ? 1 : 0);
    }
    k_classifier<<<(NN + 7) / 8, 256>>>(Wa, ba, out);
}